// round 5
// baseline (speedup 1.0000x reference)
#include <cuda_runtime.h>
#include <math.h>

#define D      128
#define ROWS   32            // rows per block in kernel 1 (static smem fits)
#define NBLK1  256           // 8192 / 32
#define TPB    256
#define EPS    1e-8f

typedef unsigned long long u64;

// Deterministic scratch (no atomics, no allocation):
__device__ float g_part[3][NBLK1][D * D];   // 3*256*16384*4B = 50.3 MB (L2-resident)
__device__ float g_diag[NBLK1];             // per-block diagonal correction
__device__ float g_bsum[256];               // combine-block sums

// ---- packed fp32x2 helpers (Blackwell FFMA2) -------------------------------
__device__ __forceinline__ u64 pack2(float lo, float hi) {
    u64 r; asm("mov.b64 %0, {%1, %2};" : "=l"(r) : "f"(lo), "f"(hi)); return r;
}
__device__ __forceinline__ void unpack2(u64 v, float& lo, float& hi) {
    asm("mov.b64 {%0, %1}, %2;" : "=f"(lo), "=f"(hi) : "l"(v));
}
__device__ __forceinline__ u64 ffma2(u64 a, u64 b, u64 c) {
    u64 d; asm("fma.rn.f32x2 %0, %1, %2, %3;" : "=l"(d) : "l"(a), "l"(b), "l"(c));
    return d;
}

// ---------------------------------------------------------------------------
// Kernel 1: per-block partial D x D Grams of row-normalized slices.
//   Gq = Qn^T Qn, Gk = Kn^T Kn, C = Qn^T Kn  over this block's 32 rows.
// ---------------------------------------------------------------------------
__global__ __launch_bounds__(TPB, 2) void gram_partial_kernel(
    const float* __restrict__ q, const float* __restrict__ k)
{
    __shared__ float qs[ROWS][D];
    __shared__ float ks[ROWS][D];
    __shared__ float s_invq[ROWS], s_invk[ROWS];
    __shared__ float s_tq[ROWS],   s_tk[ROWS];

    const int tid = threadIdx.x;
    const int bid = blockIdx.x;

    // coalesced float4 load of this block's 32x128 slices
    const float4* q4 = (const float4*)(q + (size_t)bid * ROWS * D);
    const float4* k4 = (const float4*)(k + (size_t)bid * ROWS * D);
    float4* qs4 = (float4*)&qs[0][0];
    float4* ks4 = (float4*)&ks[0][0];
    const int NV = ROWS * D / 4;  // 1024
    #pragma unroll
    for (int i = tid; i < NV; i += TPB) { qs4[i] = q4[i]; ks4[i] = k4[i]; }
    __syncthreads();

    // row norms: 8 warps x 4 rows
    {
        const int w = tid >> 5, lane = tid & 31;
        #pragma unroll
        for (int r4 = 0; r4 < 4; r4++) {
            const int r = w * 4 + r4;
            float sq = 0.f, sk_ = 0.f;
            #pragma unroll
            for (int c = lane; c < D; c += 32) {
                float a = qs[r][c]; sq  = fmaf(a, a, sq);
                float b = ks[r][c]; sk_ = fmaf(b, b, sk_);
            }
            #pragma unroll
            for (int o = 16; o; o >>= 1) {
                sq  += __shfl_xor_sync(0xffffffffu, sq,  o);
                sk_ += __shfl_xor_sync(0xffffffffu, sk_, o);
            }
            if (lane == 0) {
                float nq = sqrtf(sq), nk = sqrtf(sk_);
                float iq = 1.0f / fmaxf(nq, EPS);
                float ik = 1.0f / fmaxf(nk, EPS);
                s_invq[r] = iq; s_invk[r] = ik;
                float tq = nq * iq, tk = nk * ik;      // ||row_n|| (==1 normally)
                s_tq[r] = tq * tq; s_tk[r] = tk * tk;  // qsim_ii, ksim_ii
            }
        }
    }
    __syncthreads();

    // scale rows in place
    #pragma unroll
    for (int i = tid; i < NV; i += TPB) {
        const int r = i >> 5;  // i / (D/4)
        float4 v = qs4[i]; const float s = s_invq[r];
        v.x *= s; v.y *= s; v.z *= s; v.w *= s; qs4[i] = v;
        float4 u = ks4[i]; const float t = s_invk[r];
        u.x *= t; u.y *= t; u.z *= t; u.w *= t; ks4[i] = u;
    }
    __syncthreads();

    // diagonal correction (i==j pairs included by the F-norm identity)
    if (tid == 0) {
        float dsum = 0.f;
        #pragma unroll
        for (int r = 0; r < ROWS; r++) {
            float d = s_tq[r] - s_tk[r];
            dsum = fmaf(d, d, dsum);
        }
        g_diag[bid] = dsum;
    }

    // 8x8 register tile per thread, split 4+4 so LDS.128 is conflict-free:
    // rows {a0..a0+3} ∪ {64+a0..}, cols {b0..b0+3} ∪ {64+b0..};
    // accumulators packed pairwise along columns for FFMA2.
    const int tx = tid & 15, ty = tid >> 4;
    const int a0 = ty * 4, b0 = tx * 4;

    #pragma unroll 1
    for (int m = 0; m < 3; m++) {
        // m=0: Gq = qs^T qs ; m=1: Gk = ks^T ks ; m=2: C = qs^T ks
        const float (*A)[D] = (m == 1) ? ks : qs;
        const float (*B)[D] = (m == 0) ? qs : ks;

        u64 acc[8][4];
        #pragma unroll
        for (int i = 0; i < 8; i++)
            #pragma unroll
            for (int j = 0; j < 4; j++) acc[i][j] = 0ull;

        #pragma unroll 8
        for (int r = 0; r < ROWS; r++) {
            float4 alo = *(const float4*)&A[r][a0];
            float4 ahi = *(const float4*)&A[r][a0 + 64];
            float4 blo = *(const float4*)&B[r][b0];
            float4 bhi = *(const float4*)&B[r][b0 + 64];
            float ra[8] = {alo.x, alo.y, alo.z, alo.w, ahi.x, ahi.y, ahi.z, ahi.w};
            u64 rb2[4] = {pack2(blo.x, blo.y), pack2(blo.z, blo.w),
                          pack2(bhi.x, bhi.y), pack2(bhi.z, bhi.w)};
            #pragma unroll
            for (int i = 0; i < 8; i++) {
                u64 ad = pack2(ra[i], ra[i]);
                #pragma unroll
                for (int j = 0; j < 4; j++)
                    acc[i][j] = ffma2(ad, rb2[j], acc[i][j]);
            }
        }

        float* out = &g_part[m][bid][0];
        #pragma unroll
        for (int i = 0; i < 8; i++) {
            const int row = (i < 4) ? (a0 + i) : (64 + a0 + i - 4);
            float4 v;
            unpack2(acc[i][0], v.x, v.y); unpack2(acc[i][1], v.z, v.w);
            *(float4*)&out[row * D + b0] = v;
            unpack2(acc[i][2], v.x, v.y); unpack2(acc[i][3], v.z, v.w);
            *(float4*)&out[row * D + b0 + 64] = v;
        }
    }
}

// ---------------------------------------------------------------------------
// Kernel 2: per-entry cross-block sum (4 threads per entry), then
//   contrib(e) = Gq(e)^2 + Gk(e)^2 - 2*C(e)^2 ; block-reduce -> g_bsum
// ---------------------------------------------------------------------------
__global__ __launch_bounds__(TPB) void combine_kernel()
{
    const int tid = threadIdx.x;
    const int e   = blockIdx.x * 64 + (tid >> 2);   // 256 blocks x 64 entries
    const int bq  = (tid & 3) * (NBLK1 / 4);        // this thread's b-quarter

    float sq = 0.f, sk = 0.f, sc = 0.f;
    #pragma unroll 8
    for (int bb = 0; bb < NBLK1 / 4; bb++) {
        const int b = bq + bb;
        sq += g_part[0][b][e];
        sk += g_part[1][b][e];
        sc += g_part[2][b][e];
    }
    // combine the 4 quarter-sums of this entry (butterfly over bits 0,1)
    #pragma unroll
    for (int o = 1; o <= 2; o <<= 1) {
        sq += __shfl_xor_sync(0xffffffffu, sq, o);
        sk += __shfl_xor_sync(0xffffffffu, sk, o);
        sc += __shfl_xor_sync(0xffffffffu, sc, o);
    }
    float contrib = sq * sq + sk * sk - 2.0f * sc * sc;
    // butterfly over bits 2..4 sums the warp's 8 distinct entries
    // (lanes within a quartet are identical, so each entry counts once)
    #pragma unroll
    for (int o = 4; o <= 16; o <<= 1)
        contrib += __shfl_xor_sync(0xffffffffu, contrib, o);

    __shared__ float red[8];
    const int lane = tid & 31, w = tid >> 5;
    if (lane == 0) red[w] = contrib;
    __syncthreads();
    if (w == 0) {
        float v = (lane < 8) ? red[lane] : 0.f;
        #pragma unroll
        for (int o = 4; o; o >>= 1) v += __shfl_xor_sync(0xffffffffu, v, o);
        if (lane == 0) g_bsum[blockIdx.x] = v;
    }
}

// ---------------------------------------------------------------------------
// Kernel 3: final deterministic reduction + normalization
// ---------------------------------------------------------------------------
__global__ __launch_bounds__(256) void final_kernel(float* __restrict__ out, int n)
{
    const int t = threadIdx.x;
    float v = g_bsum[t] - g_diag[t];   // 256 combine sums minus i==j pairs

    __shared__ float red[8];
    #pragma unroll
    for (int o = 16; o; o >>= 1) v += __shfl_xor_sync(0xffffffffu, v, o);
    const int lane = t & 31, w = t >> 5;
    if (lane == 0) red[w] = v;
    __syncthreads();
    if (w == 0) {
        float x = (lane < 8) ? red[lane] : 0.f;
        #pragma unroll
        for (int o = 4; o; o >>= 1) x += __shfl_xor_sync(0xffffffffu, x, o);
        if (lane == 0) {
            double denom = (double)n * (double)(n - 1);
            out[0] = (float)((double)x / denom);
        }
    }
}

// ---------------------------------------------------------------------------
extern "C" void kernel_launch(void* const* d_in, const int* in_sizes, int n_in,
                              void* d_out, int out_size)
{
    const float* q = (const float*)d_in[0];
    const float* k = (const float*)d_in[1];
    const int n = in_sizes[0] / D;        // 8192

    gram_partial_kernel<<<n / ROWS, TPB>>>(q, k);
    combine_kernel<<<256, TPB>>>();
    final_kernel<<<1, 256>>>((float*)d_out, n);
}

// round 9
// speedup vs baseline: 1.0009x; 1.0009x over previous
#include <cuda_runtime.h>
#include <math.h>

#define D      128
#define ROWS   32            // rows per block in kernel 1 (static smem fits)
#define NBLK1  256           // 8192 / 32
#define TPB    256
#define EPS    1e-8f

typedef unsigned long long u64;

// Deterministic scratch (no atomics, no allocation):
__device__ float g_part[3][NBLK1][D * D];   // 3*256*16384*4B = 50.3 MB (L2-resident)
__device__ float g_diag[NBLK1];             // per-block diagonal correction
__device__ float g_bsum[256];               // combine-block sums

// ---- packed fp32x2 helpers (Blackwell FFMA2) -------------------------------
__device__ __forceinline__ u64 pack2(float lo, float hi) {
    u64 r; asm("mov.b64 %0, {%1, %2};" : "=l"(r) : "f"(lo), "f"(hi)); return r;
}
__device__ __forceinline__ void unpack2(u64 v, float& lo, float& hi) {
    asm("mov.b64 {%0, %1}, %2;" : "=f"(lo), "=f"(hi) : "l"(v));
}
__device__ __forceinline__ u64 ffma2(u64 a, u64 b, u64 c) {
    u64 d; asm("fma.rn.f32x2 %0, %1, %2, %3;" : "=l"(d) : "l"(a), "l"(b), "l"(c));
    return d;
}

// ---------------------------------------------------------------------------
// Kernel 1: per-block partial D x D Grams of row-normalized slices.
//   Gq = Qn^T Qn, Gk = Kn^T Kn, C = Qn^T Kn  over this block's 32 rows.
// ---------------------------------------------------------------------------
__global__ __launch_bounds__(TPB, 2) void gram_partial_kernel(
    const float* __restrict__ q, const float* __restrict__ k)
{
    __shared__ float qs[ROWS][D];
    __shared__ float ks[ROWS][D];
    __shared__ float s_invq[ROWS], s_invk[ROWS];
    __shared__ float s_tq[ROWS],   s_tk[ROWS];

    const int tid = threadIdx.x;
    const int bid = blockIdx.x;

    // coalesced float4 load of this block's 32x128 slices
    const float4* q4 = (const float4*)(q + (size_t)bid * ROWS * D);
    const float4* k4 = (const float4*)(k + (size_t)bid * ROWS * D);
    float4* qs4 = (float4*)&qs[0][0];
    float4* ks4 = (float4*)&ks[0][0];
    const int NV = ROWS * D / 4;  // 1024
    #pragma unroll
    for (int i = tid; i < NV; i += TPB) { qs4[i] = q4[i]; ks4[i] = k4[i]; }
    __syncthreads();

    // row norms: 8 warps x 4 rows
    {
        const int w = tid >> 5, lane = tid & 31;
        #pragma unroll
        for (int r4 = 0; r4 < 4; r4++) {
            const int r = w * 4 + r4;
            float sq = 0.f, sk_ = 0.f;
            #pragma unroll
            for (int c = lane; c < D; c += 32) {
                float a = qs[r][c]; sq  = fmaf(a, a, sq);
                float b = ks[r][c]; sk_ = fmaf(b, b, sk_);
            }
            #pragma unroll
            for (int o = 16; o; o >>= 1) {
                sq  += __shfl_xor_sync(0xffffffffu, sq,  o);
                sk_ += __shfl_xor_sync(0xffffffffu, sk_, o);
            }
            if (lane == 0) {
                float nq = sqrtf(sq), nk = sqrtf(sk_);
                float iq = 1.0f / fmaxf(nq, EPS);
                float ik = 1.0f / fmaxf(nk, EPS);
                s_invq[r] = iq; s_invk[r] = ik;
                float tq = nq * iq, tk = nk * ik;      // ||row_n|| (==1 normally)
                s_tq[r] = tq * tq; s_tk[r] = tk * tk;  // qsim_ii, ksim_ii
            }
        }
    }
    __syncthreads();

    // scale rows in place
    #pragma unroll
    for (int i = tid; i < NV; i += TPB) {
        const int r = i >> 5;  // i / (D/4)
        float4 v = qs4[i]; const float s = s_invq[r];
        v.x *= s; v.y *= s; v.z *= s; v.w *= s; qs4[i] = v;
        float4 u = ks4[i]; const float t = s_invk[r];
        u.x *= t; u.y *= t; u.z *= t; u.w *= t; ks4[i] = u;
    }
    __syncthreads();

    // diagonal correction (i==j pairs included by the F-norm identity)
    if (tid == 0) {
        float dsum = 0.f;
        #pragma unroll
        for (int r = 0; r < ROWS; r++) {
            float d = s_tq[r] - s_tk[r];
            dsum = fmaf(d, d, dsum);
        }
        g_diag[bid] = dsum;
    }

    // 8x8 register tile per thread, split 4+4 so LDS.128 is conflict-free.
    // Software-pipelined r-loop: prefetch r+1's smem loads before computing
    // on r's values so the 29-cyc LDS latency overlaps the FFMA2 block.
    const int tx = tid & 15, ty = tid >> 4;
    const int a0 = ty * 4, b0 = tx * 4;

    #pragma unroll 1
    for (int m = 0; m < 3; m++) {
        // m=0: Gq = qs^T qs ; m=1: Gk = ks^T ks ; m=2: C = qs^T ks
        const float (*A)[D] = (m == 1) ? ks : qs;
        const float (*B)[D] = (m == 0) ? qs : ks;

        u64 acc[8][4];
        #pragma unroll
        for (int i = 0; i < 8; i++)
            #pragma unroll
            for (int j = 0; j < 4; j++) acc[i][j] = 0ull;

        // prologue: load r = 0
        float4 alo = *(const float4*)&A[0][a0];
        float4 ahi = *(const float4*)&A[0][a0 + 64];
        float4 blo = *(const float4*)&B[0][b0];
        float4 bhi = *(const float4*)&B[0][b0 + 64];

        #pragma unroll 4
        for (int r = 0; r < ROWS; r++) {
            // prefetch next iteration (dummy re-load of row 0 on the last)
            const int rn = (r + 1 < ROWS) ? (r + 1) : 0;
            float4 palo = *(const float4*)&A[rn][a0];
            float4 pahi = *(const float4*)&A[rn][a0 + 64];
            float4 pblo = *(const float4*)&B[rn][b0];
            float4 pbhi = *(const float4*)&B[rn][b0 + 64];

            // compute on current
            float ra[8] = {alo.x, alo.y, alo.z, alo.w, ahi.x, ahi.y, ahi.z, ahi.w};
            u64 rb2[4] = {pack2(blo.x, blo.y), pack2(blo.z, blo.w),
                          pack2(bhi.x, bhi.y), pack2(bhi.z, bhi.w)};
            #pragma unroll
            for (int i = 0; i < 8; i++) {
                u64 ad = pack2(ra[i], ra[i]);
                #pragma unroll
                for (int j = 0; j < 4; j++)
                    acc[i][j] = ffma2(ad, rb2[j], acc[i][j]);
            }

            alo = palo; ahi = pahi; blo = pblo; bhi = pbhi;
        }

        float* out = &g_part[m][bid][0];
        #pragma unroll
        for (int i = 0; i < 8; i++) {
            const int row = (i < 4) ? (a0 + i) : (64 + a0 + i - 4);
            float4 v;
            unpack2(acc[i][0], v.x, v.y); unpack2(acc[i][1], v.z, v.w);
            *(float4*)&out[row * D + b0] = v;
            unpack2(acc[i][2], v.x, v.y); unpack2(acc[i][3], v.z, v.w);
            *(float4*)&out[row * D + b0 + 64] = v;
        }
    }
}

// ---------------------------------------------------------------------------
// Kernel 2: per-entry cross-block sum (4 threads per entry), then
//   contrib(e) = Gq(e)^2 + Gk(e)^2 - 2*C(e)^2 ; block-reduce -> g_bsum
// ---------------------------------------------------------------------------
__global__ __launch_bounds__(TPB) void combine_kernel()
{
    const int tid = threadIdx.x;
    const int e   = blockIdx.x * 64 + (tid >> 2);   // 256 blocks x 64 entries
    const int bq  = (tid & 3) * (NBLK1 / 4);        // this thread's b-quarter

    float sq = 0.f, sk = 0.f, sc = 0.f;
    #pragma unroll 8
    for (int bb = 0; bb < NBLK1 / 4; bb++) {
        const int b = bq + bb;
        sq += g_part[0][b][e];
        sk += g_part[1][b][e];
        sc += g_part[2][b][e];
    }
    // combine the 4 quarter-sums of this entry (butterfly over bits 0,1)
    #pragma unroll
    for (int o = 1; o <= 2; o <<= 1) {
        sq += __shfl_xor_sync(0xffffffffu, sq, o);
        sk += __shfl_xor_sync(0xffffffffu, sk, o);
        sc += __shfl_xor_sync(0xffffffffu, sc, o);
    }
    float contrib = sq * sq + sk * sk - 2.0f * sc * sc;
    // butterfly over bits 2..4 sums the warp's 8 distinct entries
    // (lanes within a quartet are identical, so each entry counts once)
    #pragma unroll
    for (int o = 4; o <= 16; o <<= 1)
        contrib += __shfl_xor_sync(0xffffffffu, contrib, o);

    __shared__ float red[8];
    const int lane = tid & 31, w = tid >> 5;
    if (lane == 0) red[w] = contrib;
    __syncthreads();
    if (w == 0) {
        float v = (lane < 8) ? red[lane] : 0.f;
        #pragma unroll
        for (int o = 4; o; o >>= 1) v += __shfl_xor_sync(0xffffffffu, v, o);
        if (lane == 0) g_bsum[blockIdx.x] = v;
    }
}

// ---------------------------------------------------------------------------
// Kernel 3: final deterministic reduction + normalization
// ---------------------------------------------------------------------------
__global__ __launch_bounds__(256) void final_kernel(float* __restrict__ out, int n)
{
    const int t = threadIdx.x;
    float v = g_bsum[t] - g_diag[t];   // 256 combine sums minus i==j pairs

    __shared__ float red[8];
    #pragma unroll
    for (int o = 16; o; o >>= 1) v += __shfl_xor_sync(0xffffffffu, v, o);
    const int lane = t & 31, w = t >> 5;
    if (lane == 0) red[w] = v;
    __syncthreads();
    if (w == 0) {
        float x = (lane < 8) ? red[lane] : 0.f;
        #pragma unroll
        for (int o = 4; o; o >>= 1) x += __shfl_xor_sync(0xffffffffu, x, o);
        if (lane == 0) {
            double denom = (double)n * (double)(n - 1);
            out[0] = (float)((double)x / denom);
        }
    }
}

// ---------------------------------------------------------------------------
extern "C" void kernel_launch(void* const* d_in, const int* in_sizes, int n_in,
                              void* d_out, int out_size)
{
    const float* q = (const float*)d_in[0];
    const float* k = (const float*)d_in[1];
    const int n = in_sizes[0] / D;        // 8192

    gram_partial_kernel<<<n / ROWS, TPB>>>(q, k);
    combine_kernel<<<256, TPB>>>();
    final_kernel<<<1, 256>>>((float*)d_out, n);
}

// round 10
// speedup vs baseline: 1.0967x; 1.0958x over previous
#include <cuda_runtime.h>
#include <math.h>

#define D      128
#define ROWS   32            // rows per block in kernel 1 (static smem fits)
#define NBLK1  256           // 8192 / 32
#define TPB    256
#define NJOBS  528           // 136 (Gq upper) + 136 (Gk upper) + 256 (C full)
#define EPS    1e-8f

typedef unsigned long long u64;

// Deterministic scratch (no atomics, no allocation):
// Strict-lower tiles of g_part[0]/g_part[1] are never written -> remain zero
// (device globals are zero-initialized); combine weights account for this.
__device__ float g_part[3][NBLK1][D * D];   // 50.3 MB (L2-resident)
__device__ float g_diag[NBLK1];             // per-block diagonal correction
__device__ float g_bsum[256];               // combine-block sums

// ---- packed fp32x2 helpers (Blackwell FFMA2) -------------------------------
__device__ __forceinline__ u64 pack2(float lo, float hi) {
    u64 r; asm("mov.b64 %0, {%1, %2};" : "=l"(r) : "f"(lo), "f"(hi)); return r;
}
__device__ __forceinline__ void unpack2(u64 v, float& lo, float& hi) {
    asm("mov.b64 {%0, %1}, %2;" : "=f"(lo), "=f"(hi) : "l"(v));
}
__device__ __forceinline__ u64 ffma2(u64 a, u64 b, u64 c) {
    u64 d; asm("fma.rn.f32x2 %0, %1, %2, %3;" : "=l"(d) : "l"(a), "l"(b), "l"(c));
    return d;
}

// ---------------------------------------------------------------------------
// Kernel 1: per-block partial D x D Grams of row-normalized slices.
//   Gq = Qn^T Qn (upper tiles), Gk = Kn^T Kn (upper tiles), C = Qn^T Kn (full)
// Flat job schedule: 528 tile-jobs over 256 threads -> 2 full passes + ragged.
// ---------------------------------------------------------------------------
__global__ __launch_bounds__(TPB, 2) void gram_partial_kernel(
    const float* __restrict__ q, const float* __restrict__ k)
{
    __shared__ float qs[ROWS][D];
    __shared__ float ks[ROWS][D];
    __shared__ float s_invq[ROWS], s_invk[ROWS];
    __shared__ float s_tq[ROWS],   s_tk[ROWS];

    const int tid = threadIdx.x;
    const int bid = blockIdx.x;

    // coalesced float4 load of this block's 32x128 slices
    const float4* q4 = (const float4*)(q + (size_t)bid * ROWS * D);
    const float4* k4 = (const float4*)(k + (size_t)bid * ROWS * D);
    float4* qs4 = (float4*)&qs[0][0];
    float4* ks4 = (float4*)&ks[0][0];
    const int NV = ROWS * D / 4;  // 1024
    #pragma unroll
    for (int i = tid; i < NV; i += TPB) { qs4[i] = q4[i]; ks4[i] = k4[i]; }
    __syncthreads();

    // row norms: 8 warps x 4 rows
    {
        const int w = tid >> 5, lane = tid & 31;
        #pragma unroll
        for (int r4 = 0; r4 < 4; r4++) {
            const int r = w * 4 + r4;
            float sq = 0.f, sk_ = 0.f;
            #pragma unroll
            for (int c = lane; c < D; c += 32) {
                float a = qs[r][c]; sq  = fmaf(a, a, sq);
                float b = ks[r][c]; sk_ = fmaf(b, b, sk_);
            }
            #pragma unroll
            for (int o = 16; o; o >>= 1) {
                sq  += __shfl_xor_sync(0xffffffffu, sq,  o);
                sk_ += __shfl_xor_sync(0xffffffffu, sk_, o);
            }
            if (lane == 0) {
                float nq = sqrtf(sq), nk = sqrtf(sk_);
                float iq = 1.0f / fmaxf(nq, EPS);
                float ik = 1.0f / fmaxf(nk, EPS);
                s_invq[r] = iq; s_invk[r] = ik;
                float tq = nq * iq, tk = nk * ik;      // ||row_n|| (==1 normally)
                s_tq[r] = tq * tq; s_tk[r] = tk * tk;  // qsim_ii, ksim_ii
            }
        }
    }
    __syncthreads();

    // scale rows in place
    #pragma unroll
    for (int i = tid; i < NV; i += TPB) {
        const int r = i >> 5;  // i / (D/4)
        float4 v = qs4[i]; const float s = s_invq[r];
        v.x *= s; v.y *= s; v.z *= s; v.w *= s; qs4[i] = v;
        float4 u = ks4[i]; const float t = s_invk[r];
        u.x *= t; u.y *= t; u.z *= t; u.w *= t; ks4[i] = u;
    }
    __syncthreads();

    // diagonal correction (i==j pairs included by the F-norm identity)
    if (tid == 0) {
        float dsum = 0.f;
        #pragma unroll
        for (int r = 0; r < ROWS; r++) {
            float d = s_tq[r] - s_tk[r];
            dsum = fmaf(d, d, dsum);
        }
        g_diag[bid] = dsum;
    }

    // 8x8 register tile per job, split 4+4 so LDS.128 is conflict-free:
    // rows {4*i0..+3} U {64+4*i0..+3}, cols {4*j0..+3} U {64+4*j0..+3}.
    // Job list: u in [0,136)   -> Gq tile (i0<=j0, triangular index)
    //           u in [136,272) -> Gk tile (i0<=j0)
    //           u in [272,528) -> C tile  (all 16x16)
    #pragma unroll 1
    for (int p = 0; p < 3; p++) {
        const int u = p * TPB + tid;
        if (u >= NJOBS) continue;

        int mat, i0, j0;
        if (u < 272) {
            mat = (u < 136) ? 0 : 1;
            int idx = u - mat * 136;
            int i = 0;
            while (idx >= 16 - i) { idx -= 16 - i; i++; }  // triangular decode
            i0 = i; j0 = i + idx;                          // i0 <= j0
        } else {
            mat = 2;
            const int v = u - 272;
            i0 = v >> 4; j0 = v & 15;
        }

        // mat=0: Gq = qs^T qs ; mat=1: Gk = ks^T ks ; mat=2: C = qs^T ks
        const float (*A)[D] = (mat == 1) ? ks : qs;
        const float (*B)[D] = (mat == 0) ? qs : ks;
        const int a0 = i0 * 4, b0 = j0 * 4;

        u64 acc[8][4];
        #pragma unroll
        for (int i = 0; i < 8; i++)
            #pragma unroll
            for (int j = 0; j < 4; j++) acc[i][j] = 0ull;

        #pragma unroll 4
        for (int r = 0; r < ROWS; r++) {
            float4 alo = *(const float4*)&A[r][a0];
            float4 ahi = *(const float4*)&A[r][a0 + 64];
            float4 blo = *(const float4*)&B[r][b0];
            float4 bhi = *(const float4*)&B[r][b0 + 64];
            float ra[8] = {alo.x, alo.y, alo.z, alo.w, ahi.x, ahi.y, ahi.z, ahi.w};
            u64 rb2[4] = {pack2(blo.x, blo.y), pack2(blo.z, blo.w),
                          pack2(bhi.x, bhi.y), pack2(bhi.z, bhi.w)};
            #pragma unroll
            for (int i = 0; i < 8; i++) {
                u64 ad = pack2(ra[i], ra[i]);
                #pragma unroll
                for (int j = 0; j < 4; j++)
                    acc[i][j] = ffma2(ad, rb2[j], acc[i][j]);
            }
        }

        float* out = &g_part[mat][bid][0];
        #pragma unroll
        for (int i = 0; i < 8; i++) {
            const int row = (i < 4) ? (a0 + i) : (64 + a0 + i - 4);
            float4 v;
            unpack2(acc[i][0], v.x, v.y); unpack2(acc[i][1], v.z, v.w);
            *(float4*)&out[row * D + b0] = v;
            unpack2(acc[i][2], v.x, v.y); unpack2(acc[i][3], v.z, v.w);
            *(float4*)&out[row * D + b0 + 64] = v;
        }
    }
}

// ---------------------------------------------------------------------------
// Kernel 2: per-entry cross-block sum (4 threads per entry), then
//   contrib(e) = w*(Gq^2 + Gk^2) - 2*C^2 ; block-reduce -> g_bsum.
// Weight w accounts for the triangle-only Gq/Gk storage:
//   rowgroup(x) = (x & 63) >> 2 identifies the 4+4 split tile row-set.
//   - different groups: pair stored once (at the i0<j0 tile) -> w = 2
//   - same group (incl. diagonal): both orderings stored     -> w = 1
//   Unwritten (lower) entries are exactly zero, contributing nothing.
// ---------------------------------------------------------------------------
__global__ __launch_bounds__(TPB) void combine_kernel()
{
    const int tid = threadIdx.x;
    const int e   = blockIdx.x * 64 + (tid >> 2);   // 256 blocks x 64 entries
    const int bq  = (tid & 3) * (NBLK1 / 4);        // this thread's b-quarter

    float sq = 0.f, sk = 0.f, sc = 0.f;
    #pragma unroll 8
    for (int bb = 0; bb < NBLK1 / 4; bb++) {
        const int b = bq + bb;
        sq += g_part[0][b][e];
        sk += g_part[1][b][e];
        sc += g_part[2][b][e];
    }
    // combine the 4 quarter-sums of this entry (butterfly over bits 0,1)
    #pragma unroll
    for (int o = 1; o <= 2; o <<= 1) {
        sq += __shfl_xor_sync(0xffffffffu, sq, o);
        sk += __shfl_xor_sync(0xffffffffu, sk, o);
        sc += __shfl_xor_sync(0xffffffffu, sc, o);
    }
    const int r = e >> 7, c = e & 127;
    const float w = (((r & 63) >> 2) == ((c & 63) >> 2)) ? 1.0f : 2.0f;
    float contrib = w * (sq * sq + sk * sk) - 2.0f * sc * sc;
    // butterfly over bits 2..4 sums the warp's 8 distinct entries
    // (lanes within a quartet are identical, so each entry counts once)
    #pragma unroll
    for (int o = 4; o <= 16; o <<= 1)
        contrib += __shfl_xor_sync(0xffffffffu, contrib, o);

    __shared__ float red[8];
    const int lane = tid & 31, wrp = tid >> 5;
    if (lane == 0) red[wrp] = contrib;
    __syncthreads();
    if (wrp == 0) {
        float v = (lane < 8) ? red[lane] : 0.f;
        #pragma unroll
        for (int o = 4; o; o >>= 1) v += __shfl_xor_sync(0xffffffffu, v, o);
        if (lane == 0) g_bsum[blockIdx.x] = v;
    }
}

// ---------------------------------------------------------------------------
// Kernel 3: final deterministic reduction + normalization
// ---------------------------------------------------------------------------
__global__ __launch_bounds__(256) void final_kernel(float* __restrict__ out, int n)
{
    const int t = threadIdx.x;
    float v = g_bsum[t] - g_diag[t];   // 256 combine sums minus i==j pairs

    __shared__ float red[8];
    #pragma unroll
    for (int o = 16; o; o >>= 1) v += __shfl_xor_sync(0xffffffffu, v, o);
    const int lane = t & 31, w = t >> 5;
    if (lane == 0) red[w] = v;
    __syncthreads();
    if (w == 0) {
        float x = (lane < 8) ? red[lane] : 0.f;
        #pragma unroll
        for (int o = 4; o; o >>= 1) x += __shfl_xor_sync(0xffffffffu, x, o);
        if (lane == 0) {
            double denom = (double)n * (double)(n - 1);
            out[0] = (float)((double)x / denom);
        }
    }
}

// ---------------------------------------------------------------------------
extern "C" void kernel_launch(void* const* d_in, const int* in_sizes, int n_in,
                              void* d_out, int out_size)
{
    const float* q = (const float*)d_in[0];
    const float* k = (const float*)d_in[1];
    const int n = in_sizes[0] / D;        // 8192

    gram_partial_kernel<<<n / ROWS, TPB>>>(q, k);
    combine_kernel<<<256, TPB>>>();
    final_kernel<<<1, 256>>>((float*)d_out, n);
}